// round 10
// baseline (speedup 1.0000x reference)
#include <cuda_runtime.h>

typedef unsigned long long u64;

#define BATCH 64
#define TLEN  2048
#define TM1   2047
#define CIN   8
#define MD    16
#define NOUT  10

#define CHUNK  64
#define NCHUNK 32            // 32*64 = 2048 >= 2047 (tail -> identity)
#define NGRP   8             // 16-thread groups per block
#define SPG    8             // steps per group
#define STR    20            // padded row stride (floats)
#define SLOT   (MD*STR)      // 320 floats per matrix slot
#define GSTR   (3*SLOT + 4)  // per-group: sA + sB + sZ + pad

// chunk partial products: [B][NCHUNK][16][16]
__device__ float g_partial[BATCH * NCHUNK * MD * MD];

// ---- packed f32x2 helpers ----
__device__ __forceinline__ float2 unpk(u64 v) {
  float2 r; asm("mov.b64 {%0,%1}, %2;" : "=f"(r.x), "=f"(r.y) : "l"(v)); return r;
}
__device__ __forceinline__ u64 pk2(float x, float y) {
  u64 r; asm("mov.b64 %0, {%1,%2};" : "=l"(r) : "f"(x), "f"(y)); return r;
}
__device__ __forceinline__ u64 bc2(float x) {
  u64 r; asm("mov.b64 %0, {%1,%1};" : "=l"(r) : "f"(x)); return r;
}
__device__ __forceinline__ void fma2(u64& d, u64 a, u64 b) {
  asm("fma.rn.f32x2 %0, %1, %2, %0;" : "+l"(d) : "l"(a), "l"(b));
}
__device__ __forceinline__ u64 fma2v(u64 a, u64 b, u64 c) {
  u64 d; asm("fma.rn.f32x2 %0, %1, %2, %3;" : "=l"(d) : "l"(a), "l"(b), "l"(c)); return d;
}
__device__ __forceinline__ u64 mul2(u64 a, u64 b) {
  u64 d; asm("mul.rn.f32x2 %0, %1, %2;" : "=l"(d) : "l"(a), "l"(b)); return d;
}

// acc += av * Brow (16 floats in smem, 16B-aligned)
__device__ __forceinline__ void row_fma(u64* acc, u64 av, const float* brow) {
  const ulonglong2* bp = reinterpret_cast<const ulonglong2*>(brow);
  ulonglong2 b0 = bp[0], b1 = bp[1], b2 = bp[2], b3 = bp[3];
  fma2(acc[0], av, b0.x); fma2(acc[1], av, b0.y);
  fma2(acc[2], av, b1.x); fma2(acc[3], av, b1.y);
  fma2(acc[4], av, b2.x); fma2(acc[5], av, b2.y);
  fma2(acc[6], av, b3.x); fma2(acc[7], av, b3.y);
}

// acc(row) += a(row, packed regs) @ Bm (16x16 in smem, row stride STR)
__device__ __forceinline__ void mm_row2(const float* __restrict__ Bm,
                                        const u64* __restrict__ a,
                                        u64* __restrict__ acc) {
#pragma unroll
  for (int kp = 0; kp < 8; kp++) {
    float2 ak = unpk(a[kp]);
    row_fma(acc, bc2(ak.x), Bm + (2 * kp) * STR);
    row_fma(acc, bc2(ak.y), Bm + (2 * kp + 1) * STR);
  }
}

__device__ __forceinline__ void store_row2(float* dst, const u64* v) {
  ulonglong2* dp = reinterpret_cast<ulonglong2*>(dst);
  dp[0] = make_ulonglong2(v[0], v[1]);
  dp[1] = make_ulonglong2(v[2], v[3]);
  dp[2] = make_ulonglong2(v[4], v[5]);
  dp[3] = make_ulonglong2(v[6], v[7]);
}
__device__ __forceinline__ void load_row2(const float* src, u64* v) {
  const ulonglong2* sp = reinterpret_cast<const ulonglong2*>(src);
  ulonglong2 a = sp[0], b = sp[1], c = sp[2], d = sp[3];
  v[0] = a.x; v[1] = a.y; v[2] = b.x; v[3] = b.y;
  v[4] = c.x; v[5] = c.y; v[6] = d.x; v[7] = d.y;
}

// pad kernel (period-3 launch pattern c,f,n -> ncu "-s 5" lands on dev_chunks)
__global__ void nopk() {}

// ---------------------------------------------------------------------------
// Kernel 1: per (batch, chunk of 64 steps). R9 core, unchanged math.
// NEW: __launch_bounds__(128, 3) -> reg cap 168 (live set ~100, no spill)
// -> 3 CTAs/SM = 12 warps, so LSU (LDS) and FMA pipes overlap across warps.
// ---------------------------------------------------------------------------
__global__ void __launch_bounds__(128, 3) dev_chunks(const float* __restrict__ X,
                                                     const float* __restrict__ A) {
  __shared__ __align__(16) float Gs[CIN * SLOT];
  __shared__ __align__(16) float slots[NGRP * GSTR];
  __shared__ float dxs[CHUNK * CIN];

  const int tid   = threadIdx.x;
  const int chunk = blockIdx.x;
  const int b     = blockIdx.y;
  const int base  = chunk * CHUNK;

  for (int idx = tid; idx < CIN * MD * MD; idx += 128) {
    int c = idx >> 8;
    int i = (idx >> 4) & 15;
    int j = idx & 15;
    Gs[c * SLOT + i * STR + j] =
        A[(i * MD + j) * CIN + c] - A[(j * MD + i) * CIN + c];
  }
  for (int idx = tid; idx < CHUNK * CIN; idx += 128) {
    int k = idx >> 3;
    int c = idx & 7;
    int t = base + k;
    float v = 0.f;
    if (t < TM1)
      v = X[(b * TLEN + t + 1) * CIN + c] - X[(b * TLEN + t) * CIN + c];
    dxs[idx] = v;
  }
  __syncthreads();

  const int grp = tid >> 4;
  const int li  = tid & 15;
  float* sA = slots + grp * GSTR;   // S + odd squarings
  float* sB = sA + SLOT;            // even squarings
  float* sZ = sB + SLOT;            // running product Z

  u64 idp[8];
#pragma unroll
  for (int p = 0; p < 8; p++)
    idp[p] = pk2((li == 2 * p) ? 1.f : 0.f, (li == 2 * p + 1) ? 1.f : 0.f);

  u64 cur[8];

  for (int kl = 0; kl < SPG; kl++) {
    const int kk = grp * SPG + kl;

    // ---- S row (packed) ----
    u64 S[8];
#pragma unroll
    for (int p = 0; p < 8; p++) S[p] = 0ull;
#pragma unroll
    for (int c = 0; c < CIN; c++) {
      u64 d2 = bc2(dxs[kk * CIN + c]);
      row_fma(S, d2, Gs + c * SLOT + li * STR);
    }

    // ---- norm: min(inf, Frobenius/sqrt(2)); warp-uniform s ----
    float rs = 0.f, fr = 0.f;
#pragma unroll
    for (int p = 0; p < 8; p++) {
      float2 t = unpk(S[p]);
      rs += fabsf(t.x) + fabsf(t.y);
      fr = fmaf(t.x, t.x, fr);
      fr = fmaf(t.y, t.y, fr);
    }
#pragma unroll
    for (int off = 1; off < 16; off <<= 1) {
      rs = fmaxf(rs, __shfl_xor_sync(0xffffffffu, rs, off));
      fr += __shfl_xor_sync(0xffffffffu, fr, off);
    }
    float nrm = fminf(rs, sqrtf(0.5f * fr));
    nrm = fmaxf(nrm, __shfl_xor_sync(0xffffffffu, nrm, 16));  // warp-uniform
    int s = 0;
    if (nrm > 0.f) {
      int e;
      frexpf(nrm, &e);   // nrm = f * 2^e, f in [0.5,1)
      s = e + 2;         // ||S/2^s|| <= 0.25
      if (s < 0) s = 0;
      if (s > 40) s = 40;
    }
    const u64 sc2 = bc2(__int_as_float((127 - s) << 23));  // exact 2^-s
#pragma unroll
    for (int p = 0; p < 8; p++) S[p] = mul2(S[p], sc2);

    // ---- store S once (trailing syncs of previous step cover old readers)
    store_row2(sA + li * STR, S);
    // init Horner from registers while the STS is in flight
    {
      const u64 c6 = bc2(1.f / 6.f);
#pragma unroll
      for (int p = 0; p < 8; p++) cur[p] = fma2v(S[p], c6, idp[p]);
    }
    __syncwarp();

    // ---- commuting-Horner Taylor-6: no syncs, S read from sA ----
#pragma unroll
    for (int k = 5; k >= 1; k--) {
      u64 acc[8];
#pragma unroll
      for (int p = 0; p < 8; p++) acc[p] = 0ull;
      mm_row2(sA, cur, acc);                  // acc = cur @ S (== S @ cur)
      const u64 inv = bc2(1.f / (float)k);
#pragma unroll
      for (int p = 0; p < 8; p++) cur[p] = fma2v(acc[p], inv, idp[p]);
    }

    // ---- warp-uniform squarings: ping-pong buffers, 1 sync each ----
    for (int q = 0; q < s; q++) {
      float* buf = (q & 1) ? sA : sB;
      store_row2(buf + li * STR, cur);
      __syncwarp();                           // store visible + old readers done
      u64 acc[8];
#pragma unroll
      for (int p = 0; p < 8; p++) acc[p] = 0ull;
      mm_row2(buf, cur, acc);
#pragma unroll
      for (int p = 0; p < 8; p++) cur[p] = acc[p];
    }

    // ---- fold: Z = M @ Z ----
    if (kl > 0) {
      u64 acc[8];
#pragma unroll
      for (int p = 0; p < 8; p++) acc[p] = 0ull;
      mm_row2(sZ, cur, acc);
#pragma unroll
      for (int p = 0; p < 8; p++) cur[p] = acc[p];
    }
    __syncwarp();                             // sZ readers done before overwrite
    store_row2(sZ + li * STR, cur);
    __syncwarp();
  }

  // ---- block tree over 8 group products (later factor on the left) ----
  __syncthreads();
  for (int cnt = NGRP; cnt > 1; cnt >>= 1) {
    int pairs = cnt >> 1;
    u64 acc[8];
    bool act = (grp < pairs);
    if (act) {
      u64 lrow[8];
      load_row2(slots + (2 * grp + 1) * GSTR + 2 * SLOT + li * STR, lrow);
#pragma unroll
      for (int p = 0; p < 8; p++) acc[p] = 0ull;
      mm_row2(slots + (2 * grp) * GSTR + 2 * SLOT, lrow, acc);
    }
    __syncthreads();
    if (act) store_row2(slots + grp * GSTR + 2 * SLOT + li * STR, acc);
    __syncthreads();
  }

  const float* Zf = slots + 2 * SLOT;  // group 0's Z slot
  for (int idx = tid; idx < MD * MD; idx += 128) {
    int i = idx >> 4, j = idx & 15;
    g_partial[(b * NCHUNK + chunk) * (MD * MD) + idx] = Zf[i * STR + j];
  }
}

// ---------------------------------------------------------------------------
// Kernel 2: per batch — tree over 32 chunk products, then linear head.
// ---------------------------------------------------------------------------
__global__ void __launch_bounds__(256) dev_finalize(const float* __restrict__ W,
                                                    const float* __restrict__ bias,
                                                    float* __restrict__ out) {
  __shared__ __align__(16) float bufs[NCHUNK * SLOT];  // 40 KB
  const int tid = threadIdx.x;
  const int b   = blockIdx.x;

  for (int idx = tid; idx < NCHUNK * MD * MD; idx += 256) {
    int cm = idx >> 8;
    int r  = idx & 255;
    bufs[cm * SLOT + (r >> 4) * STR + (r & 15)] =
        g_partial[b * NCHUNK * (MD * MD) + idx];
  }
  __syncthreads();

  const int grp = tid >> 4;
  const int li  = tid & 15;
  for (int cnt = NCHUNK; cnt > 1; cnt >>= 1) {
    int pairs = cnt >> 1;
    u64 acc[8];
    if (grp < pairs) {
      u64 lrow[8];
      load_row2(bufs + (2 * grp + 1) * SLOT + li * STR, lrow);
#pragma unroll
      for (int p = 0; p < 8; p++) acc[p] = 0ull;
      mm_row2(bufs + (2 * grp) * SLOT, lrow, acc);
    }
    __syncthreads();
    if (grp < pairs) store_row2(bufs + grp * SLOT + li * STR, acc);
    __syncthreads();
  }

  if (tid < NOUT * 16) {
    const int o = tid >> 4;
    float p = 0.f;
#pragma unroll
    for (int j = 0; j < 16; j++)
      p = fmaf(bufs[li * STR + j], W[o * 256 + li * 16 + j], p);
#pragma unroll
    for (int off = 8; off > 0; off >>= 1)
      p += __shfl_xor_sync(0xffffffffu, p, off);
    if (li == 0) out[b * NOUT + o] = p + bias[o];
  }
}

extern "C" void kernel_launch(void* const* d_in, const int* in_sizes, int n_in,
                              void* d_out, int out_size) {
  const float* X = nullptr; const float* A = nullptr;
  const float* W = nullptr; const float* bv = nullptr;
  for (int i = 0; i < n_in; i++) {
    const float* p = (const float*)d_in[i];
    switch (in_sizes[i]) {
      case BATCH * TLEN * CIN: X = p; break;   // 1048576
      case MD * MD * CIN:      A = p; break;   // 2048
      case NOUT * MD * MD:     W = p; break;   // 2560
      case NOUT:               bv = p; break;  // 10
      default: break;
    }
  }
  float* out = (float*)d_out;

  dim3 g1(NCHUNK, BATCH);
  dev_chunks<<<g1, 128>>>(X, A);      // period-3 pattern: c,f,n
  dev_finalize<<<BATCH, 256>>>(W, bv, out);
  nopk<<<1, 32>>>();                  // ncu -s 5 -> global idx 5 = dev_chunks
}

// round 11
// speedup vs baseline: 1.3084x; 1.3084x over previous
#include <cuda_runtime.h>

typedef unsigned long long u64;

#define BATCH 64
#define TLEN  2048
#define TM1   2047
#define CIN   8
#define MD    16
#define NOUT  10

#define CHUNK  64
#define NCHUNK 32            // 32*64 = 2048 >= 2047 (tail -> identity)
#define NGRP   8             // 16-thread groups per block
#define SPG    8             // steps per group
#define STR    20            // padded row stride (floats)
#define SLOT   (MD*STR)      // 320 floats per matrix slot
#define GSTR   (3*SLOT + 4)  // per-group: sA + sB + sZ + pad

// chunk partial products: [B][NCHUNK][16][16]
__device__ float g_partial[BATCH * NCHUNK * MD * MD];

// ---- packed f32x2 helpers ----
__device__ __forceinline__ float2 unpk(u64 v) {
  float2 r; asm("mov.b64 {%0,%1}, %2;" : "=f"(r.x), "=f"(r.y) : "l"(v)); return r;
}
__device__ __forceinline__ u64 pk2(float x, float y) {
  u64 r; asm("mov.b64 %0, {%1,%2};" : "=l"(r) : "f"(x), "f"(y)); return r;
}
__device__ __forceinline__ u64 bc2(float x) {
  u64 r; asm("mov.b64 %0, {%1,%1};" : "=l"(r) : "f"(x)); return r;
}
__device__ __forceinline__ void fma2(u64& d, u64 a, u64 b) {
  asm("fma.rn.f32x2 %0, %1, %2, %0;" : "+l"(d) : "l"(a), "l"(b));
}
__device__ __forceinline__ u64 fma2v(u64 a, u64 b, u64 c) {
  u64 d; asm("fma.rn.f32x2 %0, %1, %2, %3;" : "=l"(d) : "l"(a), "l"(b), "l"(c)); return d;
}
__device__ __forceinline__ u64 mul2(u64 a, u64 b) {
  u64 d; asm("mul.rn.f32x2 %0, %1, %2;" : "=l"(d) : "l"(a), "l"(b)); return d;
}

// acc += av * Brow (16 floats in smem, 16B-aligned)
__device__ __forceinline__ void row_fma(u64* acc, u64 av, const float* brow) {
  const ulonglong2* bp = reinterpret_cast<const ulonglong2*>(brow);
  ulonglong2 b0 = bp[0], b1 = bp[1], b2 = bp[2], b3 = bp[3];
  fma2(acc[0], av, b0.x); fma2(acc[1], av, b0.y);
  fma2(acc[2], av, b1.x); fma2(acc[3], av, b1.y);
  fma2(acc[4], av, b2.x); fma2(acc[5], av, b2.y);
  fma2(acc[6], av, b3.x); fma2(acc[7], av, b3.y);
}

// acc(row) += a(row, packed regs) @ Bm. "#pragma unroll 2" bounds the
// load-hoist window (2 rows = 8 u64 in flight) -> register appetite ~120
// instead of 255, which is what lets 3 CTAs/SM fit WITHOUT spills.
__device__ __forceinline__ void mm_row2(const float* __restrict__ Bm,
                                        const u64* __restrict__ a,
                                        u64* __restrict__ acc) {
#pragma unroll 2
  for (int kp = 0; kp < 8; kp++) {
    float2 ak = unpk(a[kp]);
    row_fma(acc, bc2(ak.x), Bm + (2 * kp) * STR);
    row_fma(acc, bc2(ak.y), Bm + (2 * kp + 1) * STR);
  }
}

// full-unroll variant for the tiny finalize kernel (no pressure there)
__device__ __forceinline__ void mm_row2f(const float* __restrict__ Bm,
                                         const u64* __restrict__ a,
                                         u64* __restrict__ acc) {
#pragma unroll
  for (int kp = 0; kp < 8; kp++) {
    float2 ak = unpk(a[kp]);
    row_fma(acc, bc2(ak.x), Bm + (2 * kp) * STR);
    row_fma(acc, bc2(ak.y), Bm + (2 * kp + 1) * STR);
  }
}

__device__ __forceinline__ void store_row2(float* dst, const u64* v) {
  ulonglong2* dp = reinterpret_cast<ulonglong2*>(dst);
  dp[0] = make_ulonglong2(v[0], v[1]);
  dp[1] = make_ulonglong2(v[2], v[3]);
  dp[2] = make_ulonglong2(v[4], v[5]);
  dp[3] = make_ulonglong2(v[6], v[7]);
}
__device__ __forceinline__ void load_row2(const float* src, u64* v) {
  const ulonglong2* sp = reinterpret_cast<const ulonglong2*>(src);
  ulonglong2 a = sp[0], b = sp[1], c = sp[2], d = sp[3];
  v[0] = a.x; v[1] = a.y; v[2] = b.x; v[3] = b.y;
  v[4] = c.x; v[5] = c.y; v[6] = d.x; v[7] = d.y;
}

// pad kernel (period-3 launch pattern c,f,n -> ncu "-s 5" lands on dev_chunks)
__global__ void nopk() {}

// ---------------------------------------------------------------------------
// Kernel 1: per (batch, chunk of 64 steps). R9 math, reduced register
// appetite (no idp[8]; bounded hoist window), launch_bounds(128,3):
// 3 CTAs/SM = 12 warps -> 3 independent warps/SMSP hide the mm chains.
// ---------------------------------------------------------------------------
__global__ void __launch_bounds__(128, 3) dev_chunks(const float* __restrict__ X,
                                                     const float* __restrict__ A) {
  __shared__ __align__(16) float Gs[CIN * SLOT];
  __shared__ __align__(16) float slots[NGRP * GSTR];
  __shared__ float dxs[CHUNK * CIN];

  const int tid   = threadIdx.x;
  const int chunk = blockIdx.x;
  const int b     = blockIdx.y;
  const int base  = chunk * CHUNK;

  for (int idx = tid; idx < CIN * MD * MD; idx += 128) {
    int c = idx >> 8;
    int i = (idx >> 4) & 15;
    int j = idx & 15;
    Gs[c * SLOT + i * STR + j] =
        A[(i * MD + j) * CIN + c] - A[(j * MD + i) * CIN + c];
  }
  for (int idx = tid; idx < CHUNK * CIN; idx += 128) {
    int k = idx >> 3;
    int c = idx & 7;
    int t = base + k;
    float v = 0.f;
    if (t < TM1)
      v = X[(b * TLEN + t + 1) * CIN + c] - X[(b * TLEN + t) * CIN + c];
    dxs[idx] = v;
  }
  __syncthreads();

  const int grp = tid >> 4;
  const int li  = tid & 15;
  float* sA = slots + grp * GSTR;   // S + odd squarings
  float* sB = sA + SLOT;            // even squarings
  float* sZ = sB + SLOT;            // running product Z

  // identity contribution for this thread's row: one packed reg + index
  const int didx = li >> 1;
  const u64 diagv = pk2((li & 1) ? 0.f : 1.f, (li & 1) ? 1.f : 0.f);

  u64 cur[8];

  for (int kl = 0; kl < SPG; kl++) {
    const int kk = grp * SPG + kl;

    // ---- S row (packed) ----
    u64 S[8];
#pragma unroll
    for (int p = 0; p < 8; p++) S[p] = 0ull;
#pragma unroll
    for (int c = 0; c < CIN; c++) {
      u64 d2 = bc2(dxs[kk * CIN + c]);
      row_fma(S, d2, Gs + c * SLOT + li * STR);
    }

    // ---- norm: min(inf, Frobenius/sqrt(2)); warp-uniform s ----
    float rs = 0.f, fr = 0.f;
#pragma unroll
    for (int p = 0; p < 8; p++) {
      float2 t = unpk(S[p]);
      rs += fabsf(t.x) + fabsf(t.y);
      fr = fmaf(t.x, t.x, fr);
      fr = fmaf(t.y, t.y, fr);
    }
#pragma unroll
    for (int off = 1; off < 16; off <<= 1) {
      rs = fmaxf(rs, __shfl_xor_sync(0xffffffffu, rs, off));
      fr += __shfl_xor_sync(0xffffffffu, fr, off);
    }
    float nrm = fminf(rs, sqrtf(0.5f * fr));
    nrm = fmaxf(nrm, __shfl_xor_sync(0xffffffffu, nrm, 16));  // warp-uniform
    int s = 0;
    if (nrm > 0.f) {
      int e;
      frexpf(nrm, &e);   // nrm = f * 2^e, f in [0.5,1)
      s = e + 2;         // ||S/2^s|| <= 0.25
      if (s < 0) s = 0;
      if (s > 40) s = 40;
    }
    const u64 sc2 = bc2(__int_as_float((127 - s) << 23));  // exact 2^-s
#pragma unroll
    for (int p = 0; p < 8; p++) S[p] = mul2(S[p], sc2);

    // ---- store S once (trailing syncs of previous step cover old readers)
    store_row2(sA + li * STR, S);
    // init Horner from registers while the STS is in flight
    {
      const u64 c6 = bc2(1.f / 6.f);
#pragma unroll
      for (int p = 0; p < 8; p++)
        cur[p] = fma2v(S[p], c6, (p == didx) ? diagv : 0ull);
    }
    __syncwarp();

    // ---- commuting-Horner Taylor-6: no syncs, S read from sA ----
#pragma unroll
    for (int k = 5; k >= 1; k--) {
      u64 acc[8];
#pragma unroll
      for (int p = 0; p < 8; p++) acc[p] = 0ull;
      mm_row2(sA, cur, acc);                  // acc = cur @ S (== S @ cur)
      const u64 inv = bc2(1.f / (float)k);
#pragma unroll
      for (int p = 0; p < 8; p++)
        cur[p] = fma2v(acc[p], inv, (p == didx) ? diagv : 0ull);
    }

    // ---- warp-uniform squarings: ping-pong buffers, 1 sync each ----
    for (int q = 0; q < s; q++) {
      float* buf = (q & 1) ? sA : sB;
      store_row2(buf + li * STR, cur);
      __syncwarp();                           // store visible + old readers done
      u64 acc[8];
#pragma unroll
      for (int p = 0; p < 8; p++) acc[p] = 0ull;
      mm_row2(buf, cur, acc);
#pragma unroll
      for (int p = 0; p < 8; p++) cur[p] = acc[p];
    }

    // ---- fold: Z = M @ Z ----
    if (kl > 0) {
      u64 acc[8];
#pragma unroll
      for (int p = 0; p < 8; p++) acc[p] = 0ull;
      mm_row2(sZ, cur, acc);
#pragma unroll
      for (int p = 0; p < 8; p++) cur[p] = acc[p];
    }
    __syncwarp();                             // sZ readers done before overwrite
    store_row2(sZ + li * STR, cur);
    __syncwarp();
  }

  // ---- block tree over 8 group products (later factor on the left) ----
  __syncthreads();
  for (int cnt = NGRP; cnt > 1; cnt >>= 1) {
    int pairs = cnt >> 1;
    u64 acc[8];
    bool act = (grp < pairs);
    if (act) {
      u64 lrow[8];
      load_row2(slots + (2 * grp + 1) * GSTR + 2 * SLOT + li * STR, lrow);
#pragma unroll
      for (int p = 0; p < 8; p++) acc[p] = 0ull;
      mm_row2(slots + (2 * grp) * GSTR + 2 * SLOT, lrow, acc);
    }
    __syncthreads();
    if (act) store_row2(slots + grp * GSTR + 2 * SLOT + li * STR, acc);
    __syncthreads();
  }

  const float* Zf = slots + 2 * SLOT;  // group 0's Z slot
  for (int idx = tid; idx < MD * MD; idx += 128) {
    int i = idx >> 4, j = idx & 15;
    g_partial[(b * NCHUNK + chunk) * (MD * MD) + idx] = Zf[i * STR + j];
  }
}

// ---------------------------------------------------------------------------
// Kernel 2: per batch — tree over 32 chunk products, then linear head.
// ---------------------------------------------------------------------------
__global__ void __launch_bounds__(256) dev_finalize(const float* __restrict__ W,
                                                    const float* __restrict__ bias,
                                                    float* __restrict__ out) {
  __shared__ __align__(16) float bufs[NCHUNK * SLOT];  // 40 KB
  const int tid = threadIdx.x;
  const int b   = blockIdx.x;

  for (int idx = tid; idx < NCHUNK * MD * MD; idx += 256) {
    int cm = idx >> 8;
    int r  = idx & 255;
    bufs[cm * SLOT + (r >> 4) * STR + (r & 15)] =
        g_partial[b * NCHUNK * (MD * MD) + idx];
  }
  __syncthreads();

  const int grp = tid >> 4;
  const int li  = tid & 15;
  for (int cnt = NCHUNK; cnt > 1; cnt >>= 1) {
    int pairs = cnt >> 1;
    u64 acc[8];
    if (grp < pairs) {
      u64 lrow[8];
      load_row2(bufs + (2 * grp + 1) * SLOT + li * STR, lrow);
#pragma unroll
      for (int p = 0; p < 8; p++) acc[p] = 0ull;
      mm_row2f(bufs + (2 * grp) * SLOT, lrow, acc);
    }
    __syncthreads();
    if (grp < pairs) store_row2(bufs + grp * SLOT + li * STR, acc);
    __syncthreads();
  }

  if (tid < NOUT * 16) {
    const int o = tid >> 4;
    float p = 0.f;
#pragma unroll
    for (int j = 0; j < 16; j++)
      p = fmaf(bufs[li * STR + j], W[o * 256 + li * 16 + j], p);
#pragma unroll
    for (int off = 8; off > 0; off >>= 1)
      p += __shfl_xor_sync(0xffffffffu, p, off);
    if (li == 0) out[b * NOUT + o] = p + bias[o];
  }
}

extern "C" void kernel_launch(void* const* d_in, const int* in_sizes, int n_in,
                              void* d_out, int out_size) {
  const float* X = nullptr; const float* A = nullptr;
  const float* W = nullptr; const float* bv = nullptr;
  for (int i = 0; i < n_in; i++) {
    const float* p = (const float*)d_in[i];
    switch (in_sizes[i]) {
      case BATCH * TLEN * CIN: X = p; break;   // 1048576
      case MD * MD * CIN:      A = p; break;   // 2048
      case NOUT * MD * MD:     W = p; break;   // 2560
      case NOUT:               bv = p; break;  // 10
      default: break;
    }
  }
  float* out = (float*)d_out;

  dim3 g1(NCHUNK, BATCH);
  dev_chunks<<<g1, 128>>>(X, A);      // period-3 pattern: c,f,n
  dev_finalize<<<BATCH, 256>>>(W, bv, out);
  nopk<<<1, 32>>>();                  // ncu -s 5 -> global idx 5 = dev_chunks
}

// round 12
// speedup vs baseline: 1.5821x; 1.2092x over previous
#include <cuda_runtime.h>

typedef unsigned long long u64;

#define BATCH 64
#define TLEN  2048
#define TM1   2047
#define CIN   8
#define MD    16
#define NOUT  10

#define CHUNK  64
#define NCHUNK 32            // 32*64 = 2048 >= 2047 (tail -> identity)
#define NGRP   8             // 16-thread groups per block
#define SPG    8             // steps per group
#define STR    20            // padded row stride (floats)
#define SLOT   (MD*STR)      // 320 floats per matrix slot
#define GSTR   (2*SLOT + 4)  // per-group: S/scratch slot + Z slot + pad

// chunk partial products: [B][NCHUNK][16][16]
__device__ float g_partial[BATCH * NCHUNK * MD * MD];
// per-batch arrival counters (zero-initialized; reset by the finalizing CTA
// after use, so CUDA-graph replays always start from 0)
__device__ int g_cnt[BATCH];

// shared scratch: main phase needs 8224 floats, finalize phase 32*SLOT=10240
#define SMEM_FLOATS 10560

// ---- packed f32x2 helpers ----
__device__ __forceinline__ float2 unpk(u64 v) {
  float2 r; asm("mov.b64 {%0,%1}, %2;" : "=f"(r.x), "=f"(r.y) : "l"(v)); return r;
}
__device__ __forceinline__ u64 pk2(float x, float y) {
  u64 r; asm("mov.b64 %0, {%1,%2};" : "=l"(r) : "f"(x), "f"(y)); return r;
}
__device__ __forceinline__ u64 bc2(float x) {
  u64 r; asm("mov.b64 %0, {%1,%1};" : "=l"(r) : "f"(x)); return r;
}
__device__ __forceinline__ void fma2(u64& d, u64 a, u64 b) {
  asm("fma.rn.f32x2 %0, %1, %2, %0;" : "+l"(d) : "l"(a), "l"(b));
}
__device__ __forceinline__ u64 fma2v(u64 a, u64 b, u64 c) {
  u64 d; asm("fma.rn.f32x2 %0, %1, %2, %3;" : "=l"(d) : "l"(a), "l"(b), "l"(c)); return d;
}
__device__ __forceinline__ u64 mul2(u64 a, u64 b) {
  u64 d; asm("mul.rn.f32x2 %0, %1, %2;" : "=l"(d) : "l"(a), "l"(b)); return d;
}

// acc += av * Brow (16 floats in smem, 16B-aligned)
__device__ __forceinline__ void row_fma(u64* acc, u64 av, const float* brow) {
  const ulonglong2* bp = reinterpret_cast<const ulonglong2*>(brow);
  ulonglong2 b0 = bp[0], b1 = bp[1], b2 = bp[2], b3 = bp[3];
  fma2(acc[0], av, b0.x); fma2(acc[1], av, b0.y);
  fma2(acc[2], av, b1.x); fma2(acc[3], av, b1.y);
  fma2(acc[4], av, b2.x); fma2(acc[5], av, b2.y);
  fma2(acc[6], av, b3.x); fma2(acc[7], av, b3.y);
}

// acc(row) += a(row, packed regs) @ Bm (16x16 in smem, row stride STR)
// FULL unroll: this is the champion codegen (R6); do not bound the window.
__device__ __forceinline__ void mm_row2(const float* __restrict__ Bm,
                                        const u64* __restrict__ a,
                                        u64* __restrict__ acc) {
#pragma unroll
  for (int kp = 0; kp < 8; kp++) {
    float2 ak = unpk(a[kp]);
    row_fma(acc, bc2(ak.x), Bm + (2 * kp) * STR);
    row_fma(acc, bc2(ak.y), Bm + (2 * kp + 1) * STR);
  }
}

__device__ __forceinline__ void store_row2(float* dst, const u64* v) {
  ulonglong2* dp = reinterpret_cast<ulonglong2*>(dst);
  dp[0] = make_ulonglong2(v[0], v[1]);
  dp[1] = make_ulonglong2(v[2], v[3]);
  dp[2] = make_ulonglong2(v[4], v[5]);
  dp[3] = make_ulonglong2(v[6], v[7]);
}
__device__ __forceinline__ void load_row2(const float* src, u64* v) {
  const ulonglong2* sp = reinterpret_cast<const ulonglong2*>(src);
  ulonglong2 a = sp[0], b = sp[1], c = sp[2], d = sp[3];
  v[0] = a.x; v[1] = a.y; v[2] = b.x; v[3] = b.y;
  v[4] = c.x; v[5] = c.y; v[6] = d.x; v[7] = d.y;
}

// ---------------------------------------------------------------------------
// Single fused kernel. Per (batch, chunk of 64 steps): R6's exact expm path
// (commuting-Horner Taylor-6 at theta<=0.25, warp-uniform squarings), fold,
// block tree -> chunk product -> g_partial. The LAST CTA of each batch then
// performs the 32-chunk tree + linear head (was dev_finalize).
// ---------------------------------------------------------------------------
__global__ void __launch_bounds__(128) dev_chunks(const float* __restrict__ X,
                                                  const float* __restrict__ A,
                                                  const float* __restrict__ W,
                                                  const float* __restrict__ bias,
                                                  float* __restrict__ out) {
  __shared__ __align__(16) float smem_all[SMEM_FLOATS];
  float* Gs    = smem_all;                  // CIN*SLOT = 2560
  float* slots = smem_all + CIN * SLOT;     // NGRP*GSTR = 5152
  float* dxs   = slots + NGRP * GSTR;       // CHUNK*CIN = 512

  const int tid   = threadIdx.x;
  const int chunk = blockIdx.x;
  const int b     = blockIdx.y;
  const int base  = chunk * CHUNK;

  for (int idx = tid; idx < CIN * MD * MD; idx += 128) {
    int c = idx >> 8;
    int i = (idx >> 4) & 15;
    int j = idx & 15;
    Gs[c * SLOT + i * STR + j] =
        A[(i * MD + j) * CIN + c] - A[(j * MD + i) * CIN + c];
  }
  for (int idx = tid; idx < CHUNK * CIN; idx += 128) {
    int k = idx >> 3;
    int c = idx & 7;
    int t = base + k;
    float v = 0.f;
    if (t < TM1)
      v = X[(b * TLEN + t + 1) * CIN + c] - X[(b * TLEN + t) * CIN + c];
    dxs[idx] = v;
  }
  __syncthreads();

  const int grp = tid >> 4;
  const int li  = tid & 15;
  float* gS = slots + grp * GSTR;   // S / squaring scratch
  float* gZ = gS + SLOT;            // running product Z

  // identity row (packed), per thread — champion (R6) form
  u64 idp[8];
#pragma unroll
  for (int p = 0; p < 8; p++)
    idp[p] = pk2((li == 2 * p) ? 1.f : 0.f, (li == 2 * p + 1) ? 1.f : 0.f);

  u64 cur[8];

  for (int kl = 0; kl < SPG; kl++) {
    const int kk = grp * SPG + kl;

    // ---- S row (packed) ----
    u64 S[8];
#pragma unroll
    for (int p = 0; p < 8; p++) S[p] = 0ull;
#pragma unroll
    for (int c = 0; c < CIN; c++) {
      u64 d2 = bc2(dxs[kk * CIN + c]);
      row_fma(S, d2, Gs + c * SLOT + li * STR);
    }

    // ---- norm: min(inf-norm, Frobenius/sqrt(2)); warp-uniform s ----
    float rs = 0.f, fr = 0.f;
#pragma unroll
    for (int p = 0; p < 8; p++) {
      float2 t = unpk(S[p]);
      rs += fabsf(t.x) + fabsf(t.y);
      fr = fmaf(t.x, t.x, fr);
      fr = fmaf(t.y, t.y, fr);
    }
#pragma unroll
    for (int off = 1; off < 16; off <<= 1) {
      rs = fmaxf(rs, __shfl_xor_sync(0xffffffffu, rs, off));
      fr += __shfl_xor_sync(0xffffffffu, fr, off);
    }
    float nrm = fminf(rs, sqrtf(0.5f * fr));
    nrm = fmaxf(nrm, __shfl_xor_sync(0xffffffffu, nrm, 16));  // warp-uniform
    int s = 0;
    if (nrm > 0.f) {
      int e;
      frexpf(nrm, &e);   // nrm = f * 2^e, f in [0.5,1)
      s = e + 2;         // ||S/2^s|| <= 0.25
      if (s < 0) s = 0;
      if (s > 40) s = 40;
    }
    const u64 sc2 = bc2(__int_as_float((127 - s) << 23));  // exact 2^-s
#pragma unroll
    for (int p = 0; p < 8; p++) S[p] = mul2(S[p], sc2);

    // ---- store S once; init Horner while the STS is in flight ----
    __syncwarp();
    store_row2(gS + li * STR, S);
    {
      const u64 c6 = bc2(1.f / 6.f);
#pragma unroll
      for (int p = 0; p < 8; p++) cur[p] = fma2v(S[p], c6, idp[p]);
    }
    __syncwarp();

    // ---- commuting-Horner Taylor-6: no syncs, S read from gS ----
#pragma unroll
    for (int k = 5; k >= 1; k--) {
      u64 acc[8];
#pragma unroll
      for (int p = 0; p < 8; p++) acc[p] = 0ull;
      mm_row2(gS, cur, acc);                  // acc = cur @ S (== S @ cur)
      const u64 inv = bc2(1.f / (float)k);
#pragma unroll
      for (int p = 0; p < 8; p++) cur[p] = fma2v(acc[p], inv, idp[p]);
    }

    // ---- warp-uniform squarings (scratch = gS) ----
    for (int q = 0; q < s; q++) {
      __syncwarp();
      store_row2(gS + li * STR, cur);
      __syncwarp();
      u64 acc[8];
#pragma unroll
      for (int p = 0; p < 8; p++) acc[p] = 0ull;
      mm_row2(gS, cur, acc);
#pragma unroll
      for (int p = 0; p < 8; p++) cur[p] = acc[p];
    }

    // ---- fold: Z = M @ Z ----
    if (kl > 0) {
      u64 acc[8];
#pragma unroll
      for (int p = 0; p < 8; p++) acc[p] = 0ull;
      mm_row2(gZ, cur, acc);
#pragma unroll
      for (int p = 0; p < 8; p++) cur[p] = acc[p];
    }
    __syncwarp();
    store_row2(gZ + li * STR, cur);
    __syncwarp();
  }

  // ---- block tree over 8 group products (later factor on the left) ----
  __syncthreads();
  for (int cnt = NGRP; cnt > 1; cnt >>= 1) {
    int pairs = cnt >> 1;
    u64 acc[8];
    bool act = (grp < pairs);
    if (act) {
      u64 lrow[8];
      load_row2(slots + (2 * grp + 1) * GSTR + SLOT + li * STR, lrow);
#pragma unroll
      for (int p = 0; p < 8; p++) acc[p] = 0ull;
      mm_row2(slots + (2 * grp) * GSTR + SLOT, lrow, acc);
    }
    __syncthreads();
    if (act) store_row2(slots + grp * GSTR + SLOT + li * STR, acc);
    __syncthreads();
  }

  const float* Zf = slots + SLOT;  // group 0's Z slot
  for (int idx = tid; idx < MD * MD; idx += 128) {
    int i = idx >> 4, j = idx & 15;
    g_partial[(b * NCHUNK + chunk) * (MD * MD) + idx] = Zf[i * STR + j];
  }

  // ======== fused finalize: last CTA of this batch does the 32-chunk tree ====
  __threadfence();                          // publish g_partial writes
  __shared__ int s_last;
  if (tid == 0) {
    int prev = atomicAdd(&g_cnt[b], 1);
    s_last = (prev == NCHUNK - 1) ? 1 : 0;
  }
  __syncthreads();
  if (!s_last) return;
  __threadfence();                          // order counter-read vs partial reads

  float* fbuf = smem_all;                   // 32 * SLOT = 10240 floats
  for (int idx = tid; idx < NCHUNK * MD * MD; idx += 128) {
    int cm = idx >> 8;
    int r  = idx & 255;
    fbuf[cm * SLOT + (r >> 4) * STR + (r & 15)] =
        g_partial[b * NCHUNK * (MD * MD) + idx];
  }
  __syncthreads();

  for (int cnt = NCHUNK; cnt > 1; cnt >>= 1) {
    int pairs = cnt >> 1;
    // 8 groups cover up to 16 pairs: two passes at the first level
    for (int pb = 0; pb < pairs; pb += NGRP) {
      int pr = pb + grp;
      u64 acc[8];
      bool act = (pr < pairs);
      if (act) {
        u64 lrow[8];
        load_row2(fbuf + (2 * pr + 1) * SLOT + li * STR, lrow);
#pragma unroll
        for (int p = 0; p < 8; p++) acc[p] = 0ull;
        mm_row2(fbuf + (2 * pr) * SLOT, lrow, acc);
      }
      __syncthreads();
      if (act) store_row2(fbuf + pr * SLOT + li * STR, acc);
      __syncthreads();
    }
  }

  // linear head: out[b][o] = sum_ij Z[i][j]*W[o][i*16+j] + bias[o]
  for (int o = grp; o < NOUT; o += NGRP) {
    float p = 0.f;
#pragma unroll
    for (int j = 0; j < 16; j++)
      p = fmaf(fbuf[li * STR + j], W[o * 256 + li * 16 + j], p);
#pragma unroll
    for (int off = 8; off > 0; off >>= 1)
      p += __shfl_xor_sync(0xffffffffu, p, off);
    if (li == 0) out[b * NOUT + o] = p + bias[o];
  }

  if (tid == 0) g_cnt[b] = 0;               // reset for next graph replay
}

extern "C" void kernel_launch(void* const* d_in, const int* in_sizes, int n_in,
                              void* d_out, int out_size) {
  const float* X = nullptr; const float* A = nullptr;
  const float* W = nullptr; const float* bv = nullptr;
  for (int i = 0; i < n_in; i++) {
    const float* p = (const float*)d_in[i];
    switch (in_sizes[i]) {
      case BATCH * TLEN * CIN: X = p; break;   // 1048576
      case MD * MD * CIN:      A = p; break;   // 2048
      case NOUT * MD * MD:     W = p; break;   // 2560
      case NOUT:               bv = p; break;  // 10
      default: break;
    }
  }
  float* out = (float*)d_out;

  dim3 g1(NCHUNK, BATCH);
  dev_chunks<<<g1, 128>>>(X, A, W, bv, out);  // single launch; ncu -s 5 lands here
}